// round 1
// baseline (speedup 1.0000x reference)
#include <cuda_runtime.h>
#include <cuda_bf16.h>
#include <math.h>

// Problem constants (fixed by the dataset: B=2, T=2048, DIM=2048, H=16, HKV=4, D=128)
#define BATCH 2
#define TLEN  2048
#define DIM   2048
#define NH    16
#define NKV   4
#define DH    128
#define MTOT  (BATCH * TLEN)          // 4096 rows
#define ATTN_SCALE 0.08838834764831845f  // 1/sqrt(128)
#define EPSF 1.1920929e-07f

// Scratch (device globals — no allocation allowed)
__device__ float g_q[MTOT * DIM];        // [B,T,H,D]
__device__ float g_k[MTOT * NKV * DH];   // [B,T,HKV,D]
__device__ float g_v[MTOT * NKV * DH];
__device__ float g_o[MTOT * DIM];        // attention output [B,T,H,D]

// ---------------------------------------------------------------------------
// SGEMM (NT): C[M,N] = A[M,K] * B[N,K]^T  (row-major A, row-major B)
// 128x128 block tile, BK=8, 256 threads, 8x8 per-thread tile.
// Requires M%128==0, N%128==0, K%8==0 (true for all calls here).
// ---------------------------------------------------------------------------
__global__ __launch_bounds__(256) void sgemm_nt(
    const float* __restrict__ A, const float* __restrict__ B,
    float* __restrict__ C, int M, int N, int K)
{
    __shared__ float As[8][128];
    __shared__ float Bs[8][128];

    const int tid = threadIdx.x;
    const int bm = blockIdx.y * 128;
    const int bn = blockIdx.x * 128;
    const int tx = tid % 16;
    const int ty = tid / 16;
    const int lrow = tid >> 1;          // 0..127
    const int lcol = (tid & 1) * 4;     // 0 or 4

    float acc[8][8];
#pragma unroll
    for (int i = 0; i < 8; ++i)
#pragma unroll
        for (int j = 0; j < 8; ++j) acc[i][j] = 0.f;

    const float* Aptr = A + (size_t)(bm + lrow) * K + lcol;
    const float* Bptr = B + (size_t)(bn + lrow) * K + lcol;

    for (int k0 = 0; k0 < K; k0 += 8) {
        float4 av = *(const float4*)(Aptr + k0);
        float4 bv = *(const float4*)(Bptr + k0);
        As[lcol + 0][lrow] = av.x; As[lcol + 1][lrow] = av.y;
        As[lcol + 2][lrow] = av.z; As[lcol + 3][lrow] = av.w;
        Bs[lcol + 0][lrow] = bv.x; Bs[lcol + 1][lrow] = bv.y;
        Bs[lcol + 2][lrow] = bv.z; Bs[lcol + 3][lrow] = bv.w;
        __syncthreads();

#pragma unroll
        for (int kk = 0; kk < 8; ++kk) {
            float a[8], b[8];
            *(float4*)(a)     = *(const float4*)&As[kk][ty * 8];
            *(float4*)(a + 4) = *(const float4*)&As[kk][ty * 8 + 4];
            *(float4*)(b)     = *(const float4*)&Bs[kk][tx * 8];
            *(float4*)(b + 4) = *(const float4*)&Bs[kk][tx * 8 + 4];
#pragma unroll
            for (int i = 0; i < 8; ++i)
#pragma unroll
                for (int j = 0; j < 8; ++j)
                    acc[i][j] = fmaf(a[i], b[j], acc[i][j]);
        }
        __syncthreads();
    }

#pragma unroll
    for (int i = 0; i < 8; ++i) {
        float* cp = C + (size_t)(bm + ty * 8 + i) * N + bn + tx * 8;
        float4 r0 = make_float4(acc[i][0], acc[i][1], acc[i][2], acc[i][3]);
        float4 r1 = make_float4(acc[i][4], acc[i][5], acc[i][6], acc[i][7]);
        *(float4*)(cp)     = r0;
        *(float4*)(cp + 4) = r1;
    }
}

// ---------------------------------------------------------------------------
// Fused RMSNorm + RoPE (+ q_gain and 1/sqrt(D) folded into q).
// One block (128 threads) per head-vector. blockIdx.x in [0, B*T*(H+HKV)).
// ---------------------------------------------------------------------------
__global__ __launch_bounds__(128) void norm_rope_kernel(
    float* __restrict__ q, float* __restrict__ k,
    const float* __restrict__ q_gain, int T)
{
    const int vec = blockIdx.x;
    const int hh = vec % (NH + NKV);
    const int token = vec / (NH + NKV);   // b*T + t
    const int t = token % T;
    const int tid = threadIdx.x;

    float* ptr;
    float gain;
    if (hh < NH) {
        ptr = q + ((size_t)token * NH + hh) * DH;
        gain = q_gain[hh] * ATTN_SCALE;
    } else {
        ptr = k + ((size_t)token * NKV + (hh - NH)) * DH;
        gain = 1.f;
    }

    float xv = ptr[tid];

    // sum of squares over 128 elements
    __shared__ float red[4];
    float s = xv * xv;
#pragma unroll
    for (int off = 16; off > 0; off >>= 1)
        s += __shfl_xor_sync(0xffffffffu, s, off);
    if ((tid & 31) == 0) red[tid >> 5] = s;
    __syncthreads();
    float tot = red[0] + red[1] + red[2] + red[3];
    float rn = rsqrtf(tot * (1.f / DH) + EPSF);
    float xn = xv * rn;

    __shared__ float buf[DH];
    buf[tid] = xn;
    __syncthreads();

    // RoPE: NTK-scaled base when T > 1024
    float base = 10000.f;
    if (T > 1024) base = 10000.f * powf((float)T / 1024.f, 128.f / 126.f);
    float l2b = log2f(base);

    const int i = tid & 63;
    float inv = exp2f(-(float)i * (l2b * (1.f / 64.f)));
    float ang = (float)t * inv;
    float c, sn;
    __sincosf(ang, &sn, &c);  // fast path; note: check precision in post-mortem
    // use accurate sin/cos instead to stay close to reference
    c = cosf(ang); sn = sinf(ang);

    float x1 = buf[i], x2 = buf[i + 64];
    float r = (tid < 64) ? (x1 * c + x2 * sn) : (-x1 * sn + x2 * c);
    ptr[tid] = r * gain;
}

// ---------------------------------------------------------------------------
// Flash attention (causal, GQA h -> h/4), fp32.
// Block: 256 threads handles one (b, h, 64-query tile). K/V tiles of 64.
// Thread t: owns query qt=t%64, D-slice d0=(t/64)*32 (acc of 32 floats).
// ---------------------------------------------------------------------------
#define BQ 64
#define BKT 64
#define ATTN_NT 256
#define ATTN_SMEM ((BQ*DH*3 + BQ*65 + BQ*3) * 4)

__global__ __launch_bounds__(ATTN_NT) void attn_kernel(
    const float* __restrict__ q, const float* __restrict__ k,
    const float* __restrict__ v, float* __restrict__ o, int T)
{
    extern __shared__ float sm[];
    float* Qs = sm;                      // BQ*DH
    float* Ks = Qs + BQ * DH;            // BKT*DH
    float* Vs = Ks + BKT * DH;           // BKT*DH
    float* S  = Vs + BKT * DH;           // BQ*65 (padded rows)
    float* mrow = S + BQ * 65;
    float* lrow = mrow + BQ;
    float* scl  = lrow + BQ;

    const int qb = blockIdx.x, h = blockIdx.y, b = blockIdx.z;
    const int hkv = h >> 2;              // H/HKV = 4
    const int tid = threadIdx.x;
    const int q0 = qb * BQ;

    // load Q tile (already scaled by gain/sqrt(D))
    for (int i = tid; i < BQ * DH / 4; i += ATTN_NT) {
        int r = i >> 5, c = i & 31;      // DH/4 = 32
        ((float4*)Qs)[i] =
            ((const float4*)(q + ((size_t)(b * T + q0 + r) * NH + h) * DH))[c];
    }
    if (tid < BQ) { mrow[tid] = -1e30f; lrow[tid] = 0.f; }

    const int qt = tid & 63;
    const int quarter = tid >> 6;
    const int d0 = quarter * 32;
    float4 acc[8];
#pragma unroll
    for (int i = 0; i < 8; ++i) acc[i] = make_float4(0.f, 0.f, 0.f, 0.f);

    const int nkt = qb + 1;
    for (int kt = 0; kt < nkt; ++kt) {
        __syncthreads();   // protect Ks/Vs (prev PV) and S reuse
        for (int i = tid; i < BKT * DH / 4; i += ATTN_NT) {
            int r = i >> 5, c = i & 31;
            size_t src = ((size_t)(b * T + kt * BKT + r) * NKV + hkv) * DH;
            ((float4*)Ks)[i] = ((const float4*)(k + src))[c];
            ((float4*)Vs)[i] = ((const float4*)(v + src))[c];
        }
        __syncthreads();

        // scores: each thread computes 16 (qt, kj) dots
        for (int jj = 0; jj < 16; ++jj) {
            int kj = quarter * 16 + jj;
            const float4* qr = (const float4*)(Qs + qt * DH);
            const float4* kr = (const float4*)(Ks + kj * DH);
            float s = 0.f;
#pragma unroll
            for (int d = 0; d < 32; ++d) {
                float4 a = qr[d], bb = kr[d];
                s = fmaf(a.x, bb.x, s); s = fmaf(a.y, bb.y, s);
                s = fmaf(a.z, bb.z, s); s = fmaf(a.w, bb.w, s);
            }
            int gk = kt * BKT + kj;
            S[qt * 65 + kj] = (gk <= q0 + qt) ? s : -1e30f;
        }
        __syncthreads();

        // online softmax update (one thread per query row)
        if (tid < BQ) {
            float mold = mrow[tid];
            float mnew = mold;
#pragma unroll
            for (int j = 0; j < BKT; ++j) mnew = fmaxf(mnew, S[tid * 65 + j]);
            float sc = __expf(mold - mnew);
            float ls = 0.f;
#pragma unroll
            for (int j = 0; j < BKT; ++j) {
                float p = __expf(S[tid * 65 + j] - mnew);
                S[tid * 65 + j] = p;
                ls += p;
            }
            mrow[tid] = mnew;
            lrow[tid] = lrow[tid] * sc + ls;
            scl[tid] = sc;
        }
        __syncthreads();

        // rescale + PV accumulate
        float sc = scl[qt];
#pragma unroll
        for (int i = 0; i < 8; ++i) {
            acc[i].x *= sc; acc[i].y *= sc; acc[i].z *= sc; acc[i].w *= sc;
        }
        for (int j = 0; j < BKT; ++j) {
            float p = S[qt * 65 + j];
            const float4* vr = (const float4*)(Vs + j * DH + d0);
#pragma unroll
            for (int i = 0; i < 8; ++i) {
                float4 vv = vr[i];
                acc[i].x = fmaf(p, vv.x, acc[i].x);
                acc[i].y = fmaf(p, vv.y, acc[i].y);
                acc[i].z = fmaf(p, vv.z, acc[i].z);
                acc[i].w = fmaf(p, vv.w, acc[i].w);
            }
        }
    }

    float linv = 1.f / lrow[qt];
    float4* op = (float4*)(o + ((size_t)(b * T + q0 + qt) * NH + h) * DH + d0);
#pragma unroll
    for (int i = 0; i < 8; ++i) {
        float4 r = acc[i];
        r.x *= linv; r.y *= linv; r.z *= linv; r.w *= linv;
        op[i] = r;
    }
}

// ---------------------------------------------------------------------------
extern "C" void kernel_launch(void* const* d_in, const int* in_sizes, int n_in,
                              void* d_out, int out_size)
{
    const float* x  = (const float*)d_in[0];
    const float* qw = (const float*)d_in[1];
    const float* kw = (const float*)d_in[2];
    const float* vw = (const float*)d_in[3];
    const float* ow = (const float*)d_in[4];
    const float* qg = (const float*)d_in[5];
    float* out = (float*)d_out;

    float *gq, *gk, *gv, *go;
    cudaGetSymbolAddress((void**)&gq, g_q);
    cudaGetSymbolAddress((void**)&gk, g_k);
    cudaGetSymbolAddress((void**)&gv, g_v);
    cudaGetSymbolAddress((void**)&go, g_o);

    const int M = MTOT, K = DIM;

    // Projections
    sgemm_nt<<<dim3(DIM / 128, M / 128), 256>>>(x, qw, gq, M, DIM, K);
    sgemm_nt<<<dim3((NKV * DH) / 128, M / 128), 256>>>(x, kw, gk, M, NKV * DH, K);
    sgemm_nt<<<dim3((NKV * DH) / 128, M / 128), 256>>>(x, vw, gv, M, NKV * DH, K);

    // RMSNorm + RoPE (+gain, +1/sqrt(D))
    norm_rope_kernel<<<M * (NH + NKV), 128>>>(gq, gk, qg, TLEN);

    // Flash attention
    cudaFuncSetAttribute(attn_kernel,
                         cudaFuncAttributeMaxDynamicSharedMemorySize, ATTN_SMEM);
    attn_kernel<<<dim3(TLEN / BQ, NH, BATCH), ATTN_NT, ATTN_SMEM>>>(gq, gk, gv, go, TLEN);

    // Output projection
    sgemm_nt<<<dim3(DIM / 128, M / 128), 256>>>(go, ow, out, M, DIM, K);
}

// round 3
// speedup vs baseline: 1.6534x; 1.6534x over previous
#include <cuda_runtime.h>
#include <cuda_bf16.h>
#include <math.h>
#include <stdint.h>

// Problem constants (fixed: B=2, T=2048, DIM=2048, H=16, HKV=4, D=128)
#define BATCH 2
#define TLEN  2048
#define DIM   2048
#define NH    16
#define NKV   4
#define DH    128
#define MTOT  (BATCH * TLEN)
#define ATTN_SCALE 0.08838834764831845f
#define EPSF 1.1920929e-07f

// ---------------- scratch (device globals) ---------------------------------
__device__ float g_q[MTOT * DIM];
__device__ float g_k[MTOT * NKV * DH];
__device__ float g_v[MTOT * NKV * DH];
__device__ float g_o[MTOT * DIM];

__device__ __nv_bfloat16 g_xh[MTOT * DIM],  g_xl[MTOT * DIM];
__device__ __nv_bfloat16 g_qwh[DIM * DIM],  g_qwl[DIM * DIM];
__device__ __nv_bfloat16 g_kwh[NKV*DH*DIM], g_kwl[NKV*DH*DIM];
__device__ __nv_bfloat16 g_vwh[NKV*DH*DIM], g_vwl[NKV*DH*DIM];
__device__ __nv_bfloat16 g_owh[DIM * DIM],  g_owl[DIM * DIM];
__device__ __nv_bfloat16 g_oh[MTOT * DIM],  g_ol[MTOT * DIM];

__device__ float g_cos[TLEN * 64];
__device__ float g_sin[TLEN * 64];

// ---------------------------------------------------------------------------
__device__ __forceinline__ uint32_t s2u(const void* p) {
    return (uint32_t)__cvta_generic_to_shared(p);
}
#define SWZ(o) ((o) ^ (((o) >> 3) & 0x70))

__device__ __forceinline__ void cp_async16(uint32_t saddr, const void* gaddr) {
    asm volatile("cp.async.cg.shared.global [%0], [%1], 16;\n"
                 :: "r"(saddr), "l"(gaddr));
}
__device__ __forceinline__ void ldsm4(uint32_t* r, uint32_t addr) {
    asm volatile("ldmatrix.sync.aligned.m8n8.x4.shared.b16 {%0,%1,%2,%3}, [%4];"
                 : "=r"(r[0]), "=r"(r[1]), "=r"(r[2]), "=r"(r[3]) : "r"(addr));
}
__device__ __forceinline__ void ldsm2(uint32_t* r, uint32_t addr) {
    asm volatile("ldmatrix.sync.aligned.m8n8.x2.shared.b16 {%0,%1}, [%2];"
                 : "=r"(r[0]), "=r"(r[1]) : "r"(addr));
}
__device__ __forceinline__ void mma16816(float* c, const uint32_t* a, const uint32_t* b) {
    asm volatile(
        "mma.sync.aligned.m16n8k16.row.col.f32.bf16.bf16.f32 "
        "{%0,%1,%2,%3}, {%4,%5,%6,%7}, {%8,%9}, {%0,%1,%2,%3};"
        : "+f"(c[0]), "+f"(c[1]), "+f"(c[2]), "+f"(c[3])
        : "r"(a[0]), "r"(a[1]), "r"(a[2]), "r"(a[3]), "r"(b[0]), "r"(b[1]));
}

// ---------------------------------------------------------------------------
// split fp32 -> bf16 hi + bf16 lo
// ---------------------------------------------------------------------------
__global__ __launch_bounds__(256) void split_bf16(
    const float* __restrict__ src, __nv_bfloat16* __restrict__ hi,
    __nv_bfloat16* __restrict__ lo, int n4)
{
    int i = blockIdx.x * 256 + threadIdx.x;
    if (i >= n4) return;
    float4 v = ((const float4*)src)[i];
    __nv_bfloat16 h0 = __float2bfloat16(v.x);
    __nv_bfloat16 h1 = __float2bfloat16(v.y);
    __nv_bfloat16 h2 = __float2bfloat16(v.z);
    __nv_bfloat16 h3 = __float2bfloat16(v.w);
    __nv_bfloat16 l0 = __float2bfloat16(v.x - __bfloat162float(h0));
    __nv_bfloat16 l1 = __float2bfloat16(v.y - __bfloat162float(h1));
    __nv_bfloat16 l2 = __float2bfloat16(v.z - __bfloat162float(h2));
    __nv_bfloat16 l3 = __float2bfloat16(v.w - __bfloat162float(h3));
    ((__nv_bfloat162*)hi)[2*i]   = __nv_bfloat162(h0, h1);
    ((__nv_bfloat162*)hi)[2*i+1] = __nv_bfloat162(h2, h3);
    ((__nv_bfloat162*)lo)[2*i]   = __nv_bfloat162(l0, l1);
    ((__nv_bfloat162*)lo)[2*i+1] = __nv_bfloat162(l2, l3);
}

// ---------------------------------------------------------------------------
// HMMA GEMM (NT): C[M,N] = A[M,K]*B[N,K]^T, bf16 3-split:
//   C = Ah*Bh^T + Al*Bh^T + Ah*Bl^T   (fp32 accumulate in registers)
// 128x128 CTA tile, BK=64, 8 warps (2x4), warp tile 64x32, mma.m16n8k16.
// Double-buffered cp.async. M%128==0, N%128==0, K%64==0.
// ---------------------------------------------------------------------------
#define GEMM_SMEM (2 * 32768)

__global__ __launch_bounds__(256) void gemm_tc(
    const __nv_bfloat16* __restrict__ Ah, const __nv_bfloat16* __restrict__ Al,
    const __nv_bfloat16* __restrict__ Bh, const __nv_bfloat16* __restrict__ Bl,
    float* __restrict__ C, int M, int N, int K)
{
    extern __shared__ char sm[];
    const uint32_t smem_base = s2u(sm);
    const int tid = threadIdx.x;
    const int wid = tid >> 5, lane = tid & 31;
    const int wm = wid >> 2, wn = wid & 3;     // warp grid 2x4
    const int bm = blockIdx.y * 128, bn = blockIdx.x * 128;

    const int kstages = K >> 6;
    const int S = 3 * kstages;

    float acc[4][4][4];
#pragma unroll
    for (int i = 0; i < 4; ++i)
#pragma unroll
        for (int j = 0; j < 4; ++j)
#pragma unroll
            for (int t = 0; t < 4; ++t) acc[i][j][t] = 0.f;

    // per-thread ldmatrix base addresses (swizzle folded into a row-mask)
    const int l16 = lane & 15;
    uint32_t aOff[4], aMsk[4], bOff[4], bMsk[4];
#pragma unroll
    for (int mt = 0; mt < 4; ++mt) {
        int row = wm * 64 + mt * 16 + l16;
        aOff[mt] = row * 128;                  // byte offset of row start
        aMsk[mt] = (row & 7) << 4;             // swizzle XOR mask for this row
    }
#pragma unroll
    for (int nt = 0; nt < 4; ++nt) {
        int row = wn * 32 + nt * 8 + (l16 & 7);
        bOff[nt] = row * 128;
        bMsk[nt] = (row & 7) << 4;
    }
    const uint32_t kbA = (lane >> 4) * 16;     // A: k-half select per lane
    const uint32_t kbB = ((l16 >> 3) & 1) * 16; // B: k-half select per lane

    auto load_stage = [&](int s) {
        int p = s / kstages;
        int ks = (s - p * kstages) << 6;
        const __nv_bfloat16* Ap = (p == 1) ? Al : Ah;
        const __nv_bfloat16* Bp = (p == 2) ? Bl : Bh;
        uint32_t abuf = smem_base + (s & 1) * 32768;
        uint32_t bbuf = abuf + 16384;
#pragma unroll
        for (int i = 0; i < 4; ++i) {
            int c = tid + i * 256;             // 0..1023
            int row = c >> 3, c16 = c & 7;
            cp_async16(abuf + SWZ(row * 128 + c16 * 16),
                       Ap + (size_t)(bm + row) * K + ks + c16 * 8);
        }
#pragma unroll
        for (int i = 0; i < 4; ++i) {
            int c = tid + i * 256;
            int row = c >> 3, c16 = c & 7;
            cp_async16(bbuf + SWZ(row * 128 + c16 * 16),
                       Bp + (size_t)(bn + row) * K + ks + c16 * 8);
        }
        asm volatile("cp.async.commit_group;");
    };

    load_stage(0);
    for (int s = 0; s < S; ++s) {
        if (s + 1 < S) {
            load_stage(s + 1);
            asm volatile("cp.async.wait_group 1;" ::: "memory");
        } else {
            asm volatile("cp.async.wait_group 0;" ::: "memory");
        }
        __syncthreads();

        uint32_t abuf = smem_base + (s & 1) * 32768;
        uint32_t bbuf = abuf + 16384;
#pragma unroll
        for (int kk = 0; kk < 4; ++kk) {
            uint32_t af[4][4], bfr[4][2];
            uint32_t ka = kk * 32 + kbA;
            uint32_t kb = kk * 32 + kbB;
#pragma unroll
            for (int mt = 0; mt < 4; ++mt)
                ldsm4(af[mt], abuf + aOff[mt] + (ka ^ aMsk[mt]));
#pragma unroll
            for (int nt = 0; nt < 4; ++nt)
                ldsm2(bfr[nt], bbuf + bOff[nt] + (kb ^ bMsk[nt]));
#pragma unroll
            for (int mt = 0; mt < 4; ++mt)
#pragma unroll
                for (int nt = 0; nt < 4; ++nt)
                    mma16816(acc[mt][nt], af[mt], bfr[nt]);
        }
        __syncthreads();
    }

    // epilogue
    const int er = lane >> 2, ec = (lane & 3) * 2;
#pragma unroll
    for (int mt = 0; mt < 4; ++mt) {
#pragma unroll
        for (int nt = 0; nt < 4; ++nt) {
            int r0 = bm + wm * 64 + mt * 16 + er;
            int c0 = bn + wn * 32 + nt * 8 + ec;
            *(float2*)&C[(size_t)r0 * N + c0] =
                make_float2(acc[mt][nt][0], acc[mt][nt][1]);
            *(float2*)&C[(size_t)(r0 + 8) * N + c0] =
                make_float2(acc[mt][nt][2], acc[mt][nt][3]);
        }
    }
}

// ---------------------------------------------------------------------------
// RoPE tables (T x 64)
// ---------------------------------------------------------------------------
__global__ void rope_table_kernel(float* __restrict__ cs, float* __restrict__ sn)
{
    const int t = blockIdx.x, i = threadIdx.x;
    float base = 10000.f;
    if (TLEN > 1024) base = 10000.f * powf((float)TLEN / 1024.f, 128.f / 126.f);
    float l2b = log2f(base);
    float inv = exp2f(-(float)i * (l2b * (1.f / 64.f)));
    float ang = (float)t * inv;
    cs[t * 64 + i] = cosf(ang);
    sn[t * 64 + i] = sinf(ang);
}

// ---------------------------------------------------------------------------
// Fused RMSNorm + RoPE (+ q_gain and 1/sqrt(D) folded into q).
// ---------------------------------------------------------------------------
__global__ __launch_bounds__(128) void norm_rope_kernel(
    float* __restrict__ q, float* __restrict__ k,
    const float* __restrict__ q_gain,
    const float* __restrict__ cs, const float* __restrict__ sn, int T)
{
    const int vec = blockIdx.x;
    const int hh = vec % (NH + NKV);
    const int token = vec / (NH + NKV);
    const int t = token % T;
    const int tid = threadIdx.x;

    float* ptr;
    float gain;
    if (hh < NH) {
        ptr = q + ((size_t)token * NH + hh) * DH;
        gain = q_gain[hh] * ATTN_SCALE;
    } else {
        ptr = k + ((size_t)token * NKV + (hh - NH)) * DH;
        gain = 1.f;
    }

    float xv = ptr[tid];

    __shared__ float red[4];
    float s = xv * xv;
#pragma unroll
    for (int off = 16; off > 0; off >>= 1)
        s += __shfl_xor_sync(0xffffffffu, s, off);
    if ((tid & 31) == 0) red[tid >> 5] = s;
    __syncthreads();
    float tot = red[0] + red[1] + red[2] + red[3];
    float rn = rsqrtf(tot * (1.f / DH) + EPSF);
    float xn = xv * rn;

    __shared__ float buf[DH];
    buf[tid] = xn;
    __syncthreads();

    const int i = tid & 63;
    float c  = cs[t * 64 + i];
    float si = sn[t * 64 + i];
    float x1 = buf[i], x2 = buf[i + 64];
    float r = (tid < 64) ? (x1 * c + x2 * si) : (-x1 * si + x2 * c);
    ptr[tid] = r * gain;
}

// ---------------------------------------------------------------------------
// Flash attention (causal, GQA), fp32 SIMT (unchanged).
// ---------------------------------------------------------------------------
#define BQ 64
#define BKT 64
#define ATTN_NT 256
#define ATTN_SMEM ((BQ*DH*3 + BQ*65 + BQ*3) * 4)

__global__ __launch_bounds__(ATTN_NT) void attn_kernel(
    const float* __restrict__ q, const float* __restrict__ k,
    const float* __restrict__ v, float* __restrict__ o, int T)
{
    extern __shared__ float smf[];
    float* Qs = smf;
    float* Ks = Qs + BQ * DH;
    float* Vs = Ks + BKT * DH;
    float* S  = Vs + BKT * DH;
    float* mrow = S + BQ * 65;
    float* lrow = mrow + BQ;
    float* scl  = lrow + BQ;

    const int qb = blockIdx.x, h = blockIdx.y, b = blockIdx.z;
    const int hkv = h >> 2;
    const int tid = threadIdx.x;
    const int q0 = qb * BQ;

    for (int i = tid; i < BQ * DH / 4; i += ATTN_NT) {
        int r = i >> 5, c = i & 31;
        ((float4*)Qs)[i] =
            ((const float4*)(q + ((size_t)(b * T + q0 + r) * NH + h) * DH))[c];
    }
    if (tid < BQ) { mrow[tid] = -1e30f; lrow[tid] = 0.f; }

    const int qt = tid & 63;
    const int quarter = tid >> 6;
    const int d0 = quarter * 32;
    float4 acc[8];
#pragma unroll
    for (int i = 0; i < 8; ++i) acc[i] = make_float4(0.f, 0.f, 0.f, 0.f);

    const int nkt = qb + 1;
    for (int kt = 0; kt < nkt; ++kt) {
        __syncthreads();
        for (int i = tid; i < BKT * DH / 4; i += ATTN_NT) {
            int r = i >> 5, c = i & 31;
            size_t src = ((size_t)(b * T + kt * BKT + r) * NKV + hkv) * DH;
            ((float4*)Ks)[i] = ((const float4*)(k + src))[c];
            ((float4*)Vs)[i] = ((const float4*)(v + src))[c];
        }
        __syncthreads();

        for (int jj = 0; jj < 16; ++jj) {
            int kj = quarter * 16 + jj;
            const float4* qr = (const float4*)(Qs + qt * DH);
            const float4* kr = (const float4*)(Ks + kj * DH);
            float s = 0.f;
#pragma unroll
            for (int d = 0; d < 32; ++d) {
                float4 a = qr[d], bb = kr[d];
                s = fmaf(a.x, bb.x, s); s = fmaf(a.y, bb.y, s);
                s = fmaf(a.z, bb.z, s); s = fmaf(a.w, bb.w, s);
            }
            int gk = kt * BKT + kj;
            S[qt * 65 + kj] = (gk <= q0 + qt) ? s : -1e30f;
        }
        __syncthreads();

        if (tid < BQ) {
            float mold = mrow[tid];
            float mnew = mold;
#pragma unroll
            for (int j = 0; j < BKT; ++j) mnew = fmaxf(mnew, S[tid * 65 + j]);
            float sc = __expf(mold - mnew);
            float ls = 0.f;
#pragma unroll
            for (int j = 0; j < BKT; ++j) {
                float p = __expf(S[tid * 65 + j] - mnew);
                S[tid * 65 + j] = p;
                ls += p;
            }
            mrow[tid] = mnew;
            lrow[tid] = lrow[tid] * sc + ls;
            scl[tid] = sc;
        }
        __syncthreads();

        float sc = scl[qt];
#pragma unroll
        for (int i = 0; i < 8; ++i) {
            acc[i].x *= sc; acc[i].y *= sc; acc[i].z *= sc; acc[i].w *= sc;
        }
        for (int j = 0; j < BKT; ++j) {
            float p = S[qt * 65 + j];
            const float4* vr = (const float4*)(Vs + j * DH + d0);
#pragma unroll
            for (int i = 0; i < 8; ++i) {
                float4 vv = vr[i];
                acc[i].x = fmaf(p, vv.x, acc[i].x);
                acc[i].y = fmaf(p, vv.y, acc[i].y);
                acc[i].z = fmaf(p, vv.z, acc[i].z);
                acc[i].w = fmaf(p, vv.w, acc[i].w);
            }
        }
    }

    float linv = 1.f / lrow[qt];
    float4* op = (float4*)(o + ((size_t)(b * T + q0 + qt) * NH + h) * DH + d0);
#pragma unroll
    for (int i = 0; i < 8; ++i) {
        float4 r = acc[i];
        r.x *= linv; r.y *= linv; r.z *= linv; r.w *= linv;
        op[i] = r;
    }
}

// ---------------------------------------------------------------------------
extern "C" void kernel_launch(void* const* d_in, const int* in_sizes, int n_in,
                              void* d_out, int out_size)
{
    const float* x  = (const float*)d_in[0];
    const float* qw = (const float*)d_in[1];
    const float* kw = (const float*)d_in[2];
    const float* vw = (const float*)d_in[3];
    const float* ow = (const float*)d_in[4];
    const float* qg = (const float*)d_in[5];
    float* out = (float*)d_out;

    float *gq, *gk, *gv, *go, *gcos, *gsin;
    cudaGetSymbolAddress((void**)&gq, g_q);
    cudaGetSymbolAddress((void**)&gk, g_k);
    cudaGetSymbolAddress((void**)&gv, g_v);
    cudaGetSymbolAddress((void**)&go, g_o);
    cudaGetSymbolAddress((void**)&gcos, g_cos);
    cudaGetSymbolAddress((void**)&gsin, g_sin);

    __nv_bfloat16 *xh, *xl, *qwh, *qwl, *kwh, *kwl, *vwh, *vwl, *owh, *owl, *oh, *ol;
    cudaGetSymbolAddress((void**)&xh,  g_xh);  cudaGetSymbolAddress((void**)&xl,  g_xl);
    cudaGetSymbolAddress((void**)&qwh, g_qwh); cudaGetSymbolAddress((void**)&qwl, g_qwl);
    cudaGetSymbolAddress((void**)&kwh, g_kwh); cudaGetSymbolAddress((void**)&kwl, g_kwl);
    cudaGetSymbolAddress((void**)&vwh, g_vwh); cudaGetSymbolAddress((void**)&vwl, g_vwl);
    cudaGetSymbolAddress((void**)&owh, g_owh); cudaGetSymbolAddress((void**)&owl, g_owl);
    cudaGetSymbolAddress((void**)&oh,  g_oh);  cudaGetSymbolAddress((void**)&ol,  g_ol);

    const int M = MTOT, K = DIM;

    split_bf16<<<(M*K/4 + 255)/256, 256>>>(x,  xh,  xl,  M*K/4);
    split_bf16<<<(DIM*DIM/4 + 255)/256, 256>>>(qw, qwh, qwl, DIM*DIM/4);
    split_bf16<<<(NKV*DH*DIM/4 + 255)/256, 256>>>(kw, kwh, kwl, NKV*DH*DIM/4);
    split_bf16<<<(NKV*DH*DIM/4 + 255)/256, 256>>>(vw, vwh, vwl, NKV*DH*DIM/4);
    split_bf16<<<(DIM*DIM/4 + 255)/256, 256>>>(ow, owh, owl, DIM*DIM/4);

    cudaFuncSetAttribute(gemm_tc, cudaFuncAttributeMaxDynamicSharedMemorySize, GEMM_SMEM);

    gemm_tc<<<dim3(DIM/128, M/128), 256, GEMM_SMEM>>>(xh, xl, qwh, qwl, gq, M, DIM, K);
    gemm_tc<<<dim3((NKV*DH)/128, M/128), 256, GEMM_SMEM>>>(xh, xl, kwh, kwl, gk, M, NKV*DH, K);
    gemm_tc<<<dim3((NKV*DH)/128, M/128), 256, GEMM_SMEM>>>(xh, xl, vwh, vwl, gv, M, NKV*DH, K);

    rope_table_kernel<<<TLEN, 64>>>(gcos, gsin);
    norm_rope_kernel<<<M * (NH + NKV), 128>>>(gq, gk, qg, gcos, gsin, TLEN);

    cudaFuncSetAttribute(attn_kernel, cudaFuncAttributeMaxDynamicSharedMemorySize, ATTN_SMEM);
    attn_kernel<<<dim3(TLEN/BQ, NH, BATCH), ATTN_NT, ATTN_SMEM>>>(gq, gk, gv, go, TLEN);

    split_bf16<<<(M*DIM/4 + 255)/256, 256>>>(go, oh, ol, M*DIM/4);
    gemm_tc<<<dim3(DIM/128, M/128), 256, GEMM_SMEM>>>(oh, ol, owh, owl, out, M, DIM, K);
}

// round 5
// speedup vs baseline: 4.2399x; 2.5644x over previous
#include <cuda_runtime.h>
#include <cuda_bf16.h>
#include <math.h>
#include <stdint.h>

// Problem constants (fixed: B=2, T=2048, DIM=2048, H=16, HKV=4, D=128)
#define BATCH 2
#define TLEN  2048
#define DIM   2048
#define NH    16
#define NKV   4
#define DH    128
#define MTOT  (BATCH * TLEN)
#define ATTN_SCALE 0.08838834764831845f
#define LOG2E 1.4426950408889634f
#define EPSF 1.1920929e-07f

// ---------------- scratch (device globals) ---------------------------------
__device__ float g_q[MTOT * DIM];
__device__ float g_k[MTOT * NKV * DH];
__device__ float g_v[MTOT * NKV * DH];

__device__ __nv_bfloat16 g_xh[MTOT * DIM],  g_xl[MTOT * DIM];
__device__ __nv_bfloat16 g_qwh[DIM * DIM],  g_qwl[DIM * DIM];
__device__ __nv_bfloat16 g_kwh[NKV*DH*DIM], g_kwl[NKV*DH*DIM];
__device__ __nv_bfloat16 g_vwh[NKV*DH*DIM], g_vwl[NKV*DH*DIM];
__device__ __nv_bfloat16 g_owh[DIM * DIM],  g_owl[DIM * DIM];
__device__ __nv_bfloat16 g_oh[MTOT * DIM],  g_ol[MTOT * DIM];

// bf16 hi/lo post-norm Q/K and split V for attention
__device__ __nv_bfloat16 g_qbh[MTOT * DIM],      g_qbl[MTOT * DIM];
__device__ __nv_bfloat16 g_kbh[MTOT * NKV * DH], g_kbl[MTOT * NKV * DH];
__device__ __nv_bfloat16 g_vbh[MTOT * NKV * DH], g_vbl[MTOT * NKV * DH];

__device__ float g_cos[TLEN * 64];
__device__ float g_sin[TLEN * 64];

// ---------------------------------------------------------------------------
__device__ __forceinline__ uint32_t s2u(const void* p) {
    return (uint32_t)__cvta_generic_to_shared(p);
}
#define SWZ(o) ((o) ^ (((o) >> 3) & 0x70))

__device__ __forceinline__ void cp_async16(uint32_t saddr, const void* gaddr) {
    asm volatile("cp.async.cg.shared.global [%0], [%1], 16;\n"
                 :: "r"(saddr), "l"(gaddr));
}
__device__ __forceinline__ void ldsm4(uint32_t* r, uint32_t addr) {
    asm volatile("ldmatrix.sync.aligned.m8n8.x4.shared.b16 {%0,%1,%2,%3}, [%4];"
                 : "=r"(r[0]), "=r"(r[1]), "=r"(r[2]), "=r"(r[3]) : "r"(addr));
}
__device__ __forceinline__ void ldsm4t(uint32_t* r, uint32_t addr) {
    asm volatile("ldmatrix.sync.aligned.m8n8.x4.trans.shared.b16 {%0,%1,%2,%3}, [%4];"
                 : "=r"(r[0]), "=r"(r[1]), "=r"(r[2]), "=r"(r[3]) : "r"(addr));
}
__device__ __forceinline__ void ldsm2(uint32_t* r, uint32_t addr) {
    asm volatile("ldmatrix.sync.aligned.m8n8.x2.shared.b16 {%0,%1}, [%2];"
                 : "=r"(r[0]), "=r"(r[1]) : "r"(addr));
}
__device__ __forceinline__ void mma16816(float* c, const uint32_t* a, const uint32_t* b) {
    asm volatile(
        "mma.sync.aligned.m16n8k16.row.col.f32.bf16.bf16.f32 "
        "{%0,%1,%2,%3}, {%4,%5,%6,%7}, {%8,%9}, {%0,%1,%2,%3};"
        : "+f"(c[0]), "+f"(c[1]), "+f"(c[2]), "+f"(c[3])
        : "r"(a[0]), "r"(a[1]), "r"(a[2]), "r"(a[3]), "r"(b[0]), "r"(b[1]));
}
__device__ __forceinline__ uint32_t packbf(float a, float b) {
    __nv_bfloat162 t(__float2bfloat16(a), __float2bfloat16(b));
    return *(uint32_t*)&t;
}

// ---------------------------------------------------------------------------
// split fp32 -> bf16 hi + bf16 lo
// ---------------------------------------------------------------------------
__global__ __launch_bounds__(256) void split_bf16(
    const float* __restrict__ src, __nv_bfloat16* __restrict__ hi,
    __nv_bfloat16* __restrict__ lo, int n4)
{
    int i = blockIdx.x * 256 + threadIdx.x;
    if (i >= n4) return;
    float4 v = ((const float4*)src)[i];
    __nv_bfloat16 h0 = __float2bfloat16(v.x);
    __nv_bfloat16 h1 = __float2bfloat16(v.y);
    __nv_bfloat16 h2 = __float2bfloat16(v.z);
    __nv_bfloat16 h3 = __float2bfloat16(v.w);
    __nv_bfloat16 l0 = __float2bfloat16(v.x - __bfloat162float(h0));
    __nv_bfloat16 l1 = __float2bfloat16(v.y - __bfloat162float(h1));
    __nv_bfloat16 l2 = __float2bfloat16(v.z - __bfloat162float(h2));
    __nv_bfloat16 l3 = __float2bfloat16(v.w - __bfloat162float(h3));
    ((__nv_bfloat162*)hi)[2*i]   = __nv_bfloat162(h0, h1);
    ((__nv_bfloat162*)hi)[2*i+1] = __nv_bfloat162(h2, h3);
    ((__nv_bfloat162*)lo)[2*i]   = __nv_bfloat162(l0, l1);
    ((__nv_bfloat162*)lo)[2*i+1] = __nv_bfloat162(l2, l3);
}

// ---------------------------------------------------------------------------
// HMMA GEMM (NT), bf16 3-split. (unchanged from R3, validated)
// ---------------------------------------------------------------------------
#define GEMM_SMEM (2 * 32768)

__global__ __launch_bounds__(256) void gemm_tc(
    const __nv_bfloat16* __restrict__ Ah, const __nv_bfloat16* __restrict__ Al,
    const __nv_bfloat16* __restrict__ Bh, const __nv_bfloat16* __restrict__ Bl,
    float* __restrict__ C, int M, int N, int K)
{
    extern __shared__ char sm[];
    const uint32_t smem_base = s2u(sm);
    const int tid = threadIdx.x;
    const int wid = tid >> 5, lane = tid & 31;
    const int wm = wid >> 2, wn = wid & 3;
    const int bm = blockIdx.y * 128, bn = blockIdx.x * 128;

    const int kstages = K >> 6;
    const int S = 3 * kstages;

    float acc[4][4][4];
#pragma unroll
    for (int i = 0; i < 4; ++i)
#pragma unroll
        for (int j = 0; j < 4; ++j)
#pragma unroll
            for (int t = 0; t < 4; ++t) acc[i][j][t] = 0.f;

    const int l16 = lane & 15;
    uint32_t aOff[4], aMsk[4], bOff[4], bMsk[4];
#pragma unroll
    for (int mt = 0; mt < 4; ++mt) {
        int row = wm * 64 + mt * 16 + l16;
        aOff[mt] = row * 128;
        aMsk[mt] = (row & 7) << 4;
    }
#pragma unroll
    for (int nt = 0; nt < 4; ++nt) {
        int row = wn * 32 + nt * 8 + (l16 & 7);
        bOff[nt] = row * 128;
        bMsk[nt] = (row & 7) << 4;
    }
    const uint32_t kbA = (lane >> 4) * 16;
    const uint32_t kbB = ((l16 >> 3) & 1) * 16;

    auto load_stage = [&](int s) {
        int p = s / kstages;
        int ks = (s - p * kstages) << 6;
        const __nv_bfloat16* Ap = (p == 1) ? Al : Ah;
        const __nv_bfloat16* Bp = (p == 2) ? Bl : Bh;
        uint32_t abuf = smem_base + (s & 1) * 32768;
        uint32_t bbuf = abuf + 16384;
#pragma unroll
        for (int i = 0; i < 4; ++i) {
            int c = tid + i * 256;
            int row = c >> 3, c16 = c & 7;
            cp_async16(abuf + SWZ(row * 128 + c16 * 16),
                       Ap + (size_t)(bm + row) * K + ks + c16 * 8);
        }
#pragma unroll
        for (int i = 0; i < 4; ++i) {
            int c = tid + i * 256;
            int row = c >> 3, c16 = c & 7;
            cp_async16(bbuf + SWZ(row * 128 + c16 * 16),
                       Bp + (size_t)(bn + row) * K + ks + c16 * 8);
        }
        asm volatile("cp.async.commit_group;");
    };

    load_stage(0);
    for (int s = 0; s < S; ++s) {
        if (s + 1 < S) {
            load_stage(s + 1);
            asm volatile("cp.async.wait_group 1;" ::: "memory");
        } else {
            asm volatile("cp.async.wait_group 0;" ::: "memory");
        }
        __syncthreads();

        uint32_t abuf = smem_base + (s & 1) * 32768;
        uint32_t bbuf = abuf + 16384;
#pragma unroll
        for (int kk = 0; kk < 4; ++kk) {
            uint32_t af[4][4], bfr[4][2];
            uint32_t ka = kk * 32 + kbA;
            uint32_t kb = kk * 32 + kbB;
#pragma unroll
            for (int mt = 0; mt < 4; ++mt)
                ldsm4(af[mt], abuf + aOff[mt] + (ka ^ aMsk[mt]));
#pragma unroll
            for (int nt = 0; nt < 4; ++nt)
                ldsm2(bfr[nt], bbuf + bOff[nt] + (kb ^ bMsk[nt]));
#pragma unroll
            for (int mt = 0; mt < 4; ++mt)
#pragma unroll
                for (int nt = 0; nt < 4; ++nt)
                    mma16816(acc[mt][nt], af[mt], bfr[nt]);
        }
        __syncthreads();
    }

    const int er = lane >> 2, ec = (lane & 3) * 2;
#pragma unroll
    for (int mt = 0; mt < 4; ++mt) {
#pragma unroll
        for (int nt = 0; nt < 4; ++nt) {
            int r0 = bm + wm * 64 + mt * 16 + er;
            int c0 = bn + wn * 32 + nt * 8 + ec;
            *(float2*)&C[(size_t)r0 * N + c0] =
                make_float2(acc[mt][nt][0], acc[mt][nt][1]);
            *(float2*)&C[(size_t)(r0 + 8) * N + c0] =
                make_float2(acc[mt][nt][2], acc[mt][nt][3]);
        }
    }
}

// ---------------------------------------------------------------------------
// RoPE tables (T x 64)
// ---------------------------------------------------------------------------
__global__ void rope_table_kernel(float* __restrict__ cs, float* __restrict__ sn)
{
    const int t = blockIdx.x, i = threadIdx.x;
    float base = 10000.f;
    if (TLEN > 1024) base = 10000.f * powf((float)TLEN / 1024.f, 128.f / 126.f);
    float l2b = log2f(base);
    float inv = exp2f(-(float)i * (l2b * (1.f / 64.f)));
    float ang = (float)t * inv;
    cs[t * 64 + i] = cosf(ang);
    sn[t * 64 + i] = sinf(ang);
}

// ---------------------------------------------------------------------------
// Fused RMSNorm + RoPE, emitting bf16 hi/lo directly.
// q gain folds q_gain * 1/sqrt(D) * LOG2E (softmax done base-2).
// ---------------------------------------------------------------------------
__global__ __launch_bounds__(128) void norm_rope_kernel(
    const float* __restrict__ q, const float* __restrict__ k,
    const float* __restrict__ q_gain,
    const float* __restrict__ cs, const float* __restrict__ sn,
    __nv_bfloat16* __restrict__ qh, __nv_bfloat16* __restrict__ ql,
    __nv_bfloat16* __restrict__ kh, __nv_bfloat16* __restrict__ kl, int T)
{
    const int vec = blockIdx.x;
    const int hh = vec % (NH + NKV);
    const int token = vec / (NH + NKV);
    const int t = token % T;
    const int tid = threadIdx.x;

    const float* ptr;
    __nv_bfloat16 *oh, *ol;
    float gain;
    size_t off;
    if (hh < NH) {
        off = ((size_t)token * NH + hh) * DH;
        ptr = q + off; oh = qh; ol = ql;
        gain = q_gain[hh] * (ATTN_SCALE * LOG2E);
    } else {
        off = ((size_t)token * NKV + (hh - NH)) * DH;
        ptr = k + off; oh = kh; ol = kl;
        gain = 1.f;
    }

    float xv = ptr[tid];

    __shared__ float red[4];
    float s = xv * xv;
#pragma unroll
    for (int o = 16; o > 0; o >>= 1)
        s += __shfl_xor_sync(0xffffffffu, s, o);
    if ((tid & 31) == 0) red[tid >> 5] = s;
    __syncthreads();
    float tot = red[0] + red[1] + red[2] + red[3];
    float rn = rsqrtf(tot * (1.f / DH) + EPSF);
    float xn = xv * rn;

    __shared__ float buf[DH];
    buf[tid] = xn;
    __syncthreads();

    const int i = tid & 63;
    float c  = cs[t * 64 + i];
    float si = sn[t * 64 + i];
    float x1 = buf[i], x2 = buf[i + 64];
    float r = ((tid < 64) ? (x1 * c + x2 * si) : (-x1 * si + x2 * c)) * gain;

    __nv_bfloat16 hv = __float2bfloat16(r);
    __nv_bfloat16 lv = __float2bfloat16(r - __bfloat162float(hv));
    oh[off + tid] = hv;
    ol[off + tid] = lv;
}

// ---------------------------------------------------------------------------
// HMMA flash attention (causal, GQA), full hi/lo split:
//   S = qh*kh + ql*kh + qh*kl ;  O += ph*vh + pl*vh + ph*vl
// CTA: 4 warps, 64 queries (16 rows/warp) x 64-key tiles, D=128.
// smem: Q(h,l) + K(h,l) + V(h,l) = 6 x 16KB = 96KB. Rows are 256B, swizzled.
// ---------------------------------------------------------------------------
#define ATTN_SMEM (6 * 16384)

__global__ __launch_bounds__(128) void attn_mma(
    const __nv_bfloat16* __restrict__ qh, const __nv_bfloat16* __restrict__ ql,
    const __nv_bfloat16* __restrict__ kh, const __nv_bfloat16* __restrict__ kl,
    const __nv_bfloat16* __restrict__ vh, const __nv_bfloat16* __restrict__ vl,
    __nv_bfloat16* __restrict__ oh, __nv_bfloat16* __restrict__ ol)
{
    extern __shared__ char smc[];
    const uint32_t sQH = s2u(smc);
    const uint32_t sQL = sQH + 16384;
    const uint32_t sKH = sQL + 16384;
    const uint32_t sKL = sKH + 16384;
    const uint32_t sVH = sKL + 16384;
    const uint32_t sVL = sVH + 16384;

    const int qb = blockIdx.x, h = blockIdx.y, b = blockIdx.z;
    const int hkv = h >> 2;
    const int tid = threadIdx.x, wid = tid >> 5, lane = tid & 31;
    const int quad = lane >> 2, qx = lane & 3;
    const int q0 = qb * 64;

    // Q tile load (hi+lo): 64 rows x 16 x 16B chunks each
    for (int i = tid; i < 1024; i += 128) {
        int row = i >> 4, cb = (i & 15) * 16;
        uint32_t sw = row * 256 + (cb ^ ((row & 7) << 4));
        size_t g = ((size_t)(b * TLEN + q0 + row) * NH + h) * DH + (i & 15) * 8;
        cp_async16(sQH + sw, qh + g);
        cp_async16(sQL + sw, ql + g);
    }
    asm volatile("cp.async.commit_group;");

    float acc[16][4];
#pragma unroll
    for (int j = 0; j < 16; ++j)
#pragma unroll
        for (int t = 0; t < 4; ++t) acc[j][t] = 0.f;
    float m0 = -1e30f, m1 = -1e30f, l0 = 0.f, l1 = 0.f;

    const uint32_t aRow = wid * 16 + (lane & 15);
    const uint32_t aSwz = (aRow & 7) << 4;
    const uint32_t aKb  = (lane >> 4) * 16;
    const uint32_t kRowB = ((lane >> 4) & 1) * 8 + (lane & 7);  // + jj*16
    const uint32_t kKb   = ((lane >> 3) & 1) * 16;              // + kk*32
    const uint32_t vRowB = ((lane >> 3) & 1) * 8 + (lane & 7);  // + kk*16
    const uint32_t vCb   = ((lane >> 4) & 1) * 16;              // + jp*32

    for (int kt = 0; kt <= qb; ++kt) {
        __syncthreads();
        for (int i = tid; i < 1024; i += 128) {
            int row = i >> 4, cb = (i & 15) * 16;
            uint32_t sw = row * 256 + (cb ^ ((row & 7) << 4));
            size_t g = ((size_t)(b * TLEN + kt * 64 + row) * NKV + hkv) * DH + (i & 15) * 8;
            cp_async16(sKH + sw, kh + g);
            cp_async16(sKL + sw, kl + g);
            cp_async16(sVH + sw, vh + g);
            cp_async16(sVL + sw, vl + g);
        }
        asm volatile("cp.async.commit_group;");
        asm volatile("cp.async.wait_group 0;" ::: "memory");
        __syncthreads();

        // ---- S = Q K^T (3 splits, fp32 acc) ----
        float s[8][4];
#pragma unroll
        for (int j = 0; j < 8; ++j)
#pragma unroll
            for (int t = 0; t < 4; ++t) s[j][t] = 0.f;

#pragma unroll
        for (int sp = 0; sp < 3; ++sp) {
            uint32_t qbuf = (sp == 1) ? sQL : sQH;
            uint32_t kbuf = (sp == 2) ? sKL : sKH;
#pragma unroll
            for (int kk = 0; kk < 8; ++kk) {
                uint32_t af[4];
                ldsm4(af, qbuf + aRow * 256 + ((kk * 32 + aKb) ^ aSwz));
#pragma unroll
                for (int jj = 0; jj < 4; ++jj) {
                    uint32_t bf4[4];
                    uint32_t kr = jj * 16 + kRowB;
                    ldsm4(bf4, kbuf + kr * 256 + ((kk * 32 + kKb) ^ ((kr & 7) << 4)));
                    mma16816(s[2 * jj],     af, bf4);
                    mma16816(s[2 * jj + 1], af, bf4 + 2);
                }
            }
        }

        // ---- causal mask (diagonal tile only) ----
        if (kt == qb) {
            int gr = wid * 16 + quad;
#pragma unroll
            for (int j = 0; j < 8; ++j) {
                int gc = j * 8 + qx * 2;
                if (gc     > gr)     s[j][0] = -1e30f;
                if (gc + 1 > gr)     s[j][1] = -1e30f;
                if (gc     > gr + 8) s[j][2] = -1e30f;
                if (gc + 1 > gr + 8) s[j][3] = -1e30f;
            }
        }

        // ---- online softmax (base-2; LOG2E folded into q) ----
        float t0 = -1e30f, t1 = -1e30f;
#pragma unroll
        for (int j = 0; j < 8; ++j) {
            t0 = fmaxf(t0, fmaxf(s[j][0], s[j][1]));
            t1 = fmaxf(t1, fmaxf(s[j][2], s[j][3]));
        }
        t0 = fmaxf(t0, __shfl_xor_sync(0xffffffffu, t0, 1));
        t0 = fmaxf(t0, __shfl_xor_sync(0xffffffffu, t0, 2));
        t1 = fmaxf(t1, __shfl_xor_sync(0xffffffffu, t1, 1));
        t1 = fmaxf(t1, __shfl_xor_sync(0xffffffffu, t1, 2));
        float mn0 = fmaxf(m0, t0), mn1 = fmaxf(m1, t1);
        float sc0 = exp2f(m0 - mn0), sc1 = exp2f(m1 - mn1);
        m0 = mn0; m1 = mn1;

        uint32_t phA[8], phB[8], plA[8], plB[8];
        float ls0 = 0.f, ls1 = 0.f;
#pragma unroll
        for (int j = 0; j < 8; ++j) {
            float p0 = exp2f(s[j][0] - mn0);
            float p1 = exp2f(s[j][1] - mn0);
            float p2 = exp2f(s[j][2] - mn1);
            float p3 = exp2f(s[j][3] - mn1);
            ls0 += p0 + p1; ls1 += p2 + p3;
            __nv_bfloat16 h0 = __float2bfloat16(p0), h1 = __float2bfloat16(p1);
            __nv_bfloat16 h2 = __float2bfloat16(p2), h3 = __float2bfloat16(p3);
            __nv_bfloat162 a(h0, h1), bb(h2, h3);
            phA[j] = *(uint32_t*)&a; phB[j] = *(uint32_t*)&bb;
            plA[j] = packbf(p0 - __bfloat162float(h0), p1 - __bfloat162float(h1));
            plB[j] = packbf(p2 - __bfloat162float(h2), p3 - __bfloat162float(h3));
        }
        l0 = l0 * sc0 + ls0;
        l1 = l1 * sc1 + ls1;
#pragma unroll
        for (int j = 0; j < 16; ++j) {
            acc[j][0] *= sc0; acc[j][1] *= sc0;
            acc[j][2] *= sc1; acc[j][3] *= sc1;
        }

        // ---- O += P V (3 splits); n-dim = D/8 = 16 -> jp over 8 x n16 ----
#pragma unroll
        for (int sp = 0; sp < 3; ++sp) {
            const uint32_t* PA = (sp == 1) ? plA : phA;
            const uint32_t* PB = (sp == 1) ? plB : phB;
            uint32_t vbuf = (sp == 2) ? sVL : sVH;
#pragma unroll
            for (int kk = 0; kk < 4; ++kk) {
                uint32_t a[4] = {PA[2 * kk], PB[2 * kk], PA[2 * kk + 1], PB[2 * kk + 1]};
                uint32_t vr = kk * 16 + vRowB;
                uint32_t vsw = (vr & 7) << 4;
#pragma unroll
                for (int jp = 0; jp < 8; ++jp) {      // FIX: full D=128 (was 4)
                    uint32_t bv[4];
                    ldsm4t(bv, vbuf + vr * 256 + ((jp * 32 + vCb) ^ vsw));
                    mma16816(acc[2 * jp],     a, bv);
                    mma16816(acc[2 * jp + 1], a, bv + 2);
                }
            }
        }
    }

    // ---- epilogue ----
    l0 += __shfl_xor_sync(0xffffffffu, l0, 1);
    l0 += __shfl_xor_sync(0xffffffffu, l0, 2);
    l1 += __shfl_xor_sync(0xffffffffu, l1, 1);
    l1 += __shfl_xor_sync(0xffffffffu, l1, 2);
    float i0 = 1.f / l0, i1 = 1.f / l1;

    size_t tok0 = (size_t)(b * TLEN + q0 + wid * 16 + quad);
    size_t tok1 = tok0 + 8;
#pragma unroll
    for (int j = 0; j < 16; ++j) {
        int col = h * DH + j * 8 + qx * 2;
        float v0 = acc[j][0] * i0, v1 = acc[j][1] * i0;
        float v2 = acc[j][2] * i1, v3 = acc[j][3] * i1;
        __nv_bfloat16 h0 = __float2bfloat16(v0), h1 = __float2bfloat16(v1);
        __nv_bfloat16 h2 = __float2bfloat16(v2), h3 = __float2bfloat16(v3);
        *(__nv_bfloat162*)&oh[tok0 * DIM + col] = __nv_bfloat162(h0, h1);
        *(__nv_bfloat162*)&oh[tok1 * DIM + col] = __nv_bfloat162(h2, h3);
        *(__nv_bfloat162*)&ol[tok0 * DIM + col] =
            __nv_bfloat162(__float2bfloat16(v0 - __bfloat162float(h0)),
                           __float2bfloat16(v1 - __bfloat162float(h1)));
        *(__nv_bfloat162*)&ol[tok1 * DIM + col] =
            __nv_bfloat162(__float2bfloat16(v2 - __bfloat162float(h2)),
                           __float2bfloat16(v3 - __bfloat162float(h3)));
    }
}

// ---------------------------------------------------------------------------
extern "C" void kernel_launch(void* const* d_in, const int* in_sizes, int n_in,
                              void* d_out, int out_size)
{
    const float* x  = (const float*)d_in[0];
    const float* qw = (const float*)d_in[1];
    const float* kw = (const float*)d_in[2];
    const float* vw = (const float*)d_in[3];
    const float* ow = (const float*)d_in[4];
    const float* qg = (const float*)d_in[5];
    float* out = (float*)d_out;

    float *gq, *gk, *gv, *gcos, *gsin;
    cudaGetSymbolAddress((void**)&gq, g_q);
    cudaGetSymbolAddress((void**)&gk, g_k);
    cudaGetSymbolAddress((void**)&gv, g_v);
    cudaGetSymbolAddress((void**)&gcos, g_cos);
    cudaGetSymbolAddress((void**)&gsin, g_sin);

    __nv_bfloat16 *xh, *xl, *qwh, *qwl, *kwh, *kwl, *vwh, *vwl, *owh, *owl, *oh, *ol;
    __nv_bfloat16 *qbh, *qbl, *kbh, *kbl, *vbh, *vbl;
    cudaGetSymbolAddress((void**)&xh,  g_xh);  cudaGetSymbolAddress((void**)&xl,  g_xl);
    cudaGetSymbolAddress((void**)&qwh, g_qwh); cudaGetSymbolAddress((void**)&qwl, g_qwl);
    cudaGetSymbolAddress((void**)&kwh, g_kwh); cudaGetSymbolAddress((void**)&kwl, g_kwl);
    cudaGetSymbolAddress((void**)&vwh, g_vwh); cudaGetSymbolAddress((void**)&vwl, g_vwl);
    cudaGetSymbolAddress((void**)&owh, g_owh); cudaGetSymbolAddress((void**)&owl, g_owl);
    cudaGetSymbolAddress((void**)&oh,  g_oh);  cudaGetSymbolAddress((void**)&ol,  g_ol);
    cudaGetSymbolAddress((void**)&qbh, g_qbh); cudaGetSymbolAddress((void**)&qbl, g_qbl);
    cudaGetSymbolAddress((void**)&kbh, g_kbh); cudaGetSymbolAddress((void**)&kbl, g_kbl);
    cudaGetSymbolAddress((void**)&vbh, g_vbh); cudaGetSymbolAddress((void**)&vbl, g_vbl);

    const int M = MTOT, K = DIM;

    split_bf16<<<(M*K/4 + 255)/256, 256>>>(x,  xh,  xl,  M*K/4);
    split_bf16<<<(DIM*DIM/4 + 255)/256, 256>>>(qw, qwh, qwl, DIM*DIM/4);
    split_bf16<<<(NKV*DH*DIM/4 + 255)/256, 256>>>(kw, kwh, kwl, NKV*DH*DIM/4);
    split_bf16<<<(NKV*DH*DIM/4 + 255)/256, 256>>>(vw, vwh, vwl, NKV*DH*DIM/4);
    split_bf16<<<(DIM*DIM/4 + 255)/256, 256>>>(ow, owh, owl, DIM*DIM/4);

    cudaFuncSetAttribute(gemm_tc, cudaFuncAttributeMaxDynamicSharedMemorySize, GEMM_SMEM);

    gemm_tc<<<dim3(DIM/128, M/128), 256, GEMM_SMEM>>>(xh, xl, qwh, qwl, gq, M, DIM, K);
    gemm_tc<<<dim3((NKV*DH)/128, M/128), 256, GEMM_SMEM>>>(xh, xl, kwh, kwl, gk, M, NKV*DH, K);
    gemm_tc<<<dim3((NKV*DH)/128, M/128), 256, GEMM_SMEM>>>(xh, xl, vwh, vwl, gv, M, NKV*DH, K);

    rope_table_kernel<<<TLEN, 64>>>(gcos, gsin);
    norm_rope_kernel<<<M * (NH + NKV), 128>>>(gq, gk, qg, gcos, gsin,
                                              qbh, qbl, kbh, kbl, TLEN);
    split_bf16<<<(M*NKV*DH/4 + 255)/256, 256>>>(gv, vbh, vbl, M*NKV*DH/4);

    cudaFuncSetAttribute(attn_mma, cudaFuncAttributeMaxDynamicSharedMemorySize, ATTN_SMEM);
    attn_mma<<<dim3(TLEN/64, NH, BATCH), 128, ATTN_SMEM>>>(
        qbh, qbl, kbh, kbl, vbh, vbl, oh, ol);

    gemm_tc<<<dim3(DIM/128, M/128), 256, GEMM_SMEM>>>(oh, ol, owh, owl, out, M, DIM, K);
}

// round 6
// speedup vs baseline: 4.6119x; 1.0877x over previous
#include <cuda_runtime.h>
#include <cuda_bf16.h>
#include <math.h>
#include <stdint.h>

// Problem constants (fixed: B=2, T=2048, DIM=2048, H=16, HKV=4, D=128)
#define BATCH 2
#define TLEN  2048
#define DIM   2048
#define NH    16
#define NKV   4
#define DH    128
#define MTOT  (BATCH * TLEN)
#define NQKV  (DIM + 2 * NKV * DH)     // 3072 packed output cols
#define NQT   (TLEN / 64)              // 32 query tiles
#define ATTN_SCALE 0.08838834764831845f
#define LOG2E 1.4426950408889634f
#define EPSF 1.1920929e-07f

// ---------------- scratch (device globals) ---------------------------------
__device__ float g_qkv[MTOT * NQKV];   // packed q|k|v fp32

__device__ __nv_bfloat16 g_xh[MTOT * DIM],   g_xl[MTOT * DIM];
__device__ __nv_bfloat16 g_wqkvh[NQKV * DIM], g_wqkvl[NQKV * DIM];
__device__ __nv_bfloat16 g_owh[DIM * DIM],   g_owl[DIM * DIM];
__device__ __nv_bfloat16 g_oh[MTOT * DIM],   g_ol[MTOT * DIM];

__device__ __nv_bfloat16 g_qbh[MTOT * DIM],      g_qbl[MTOT * DIM];
__device__ __nv_bfloat16 g_kbh[MTOT * NKV * DH], g_kbl[MTOT * NKV * DH];
__device__ __nv_bfloat16 g_vbh[MTOT * NKV * DH], g_vbl[MTOT * NKV * DH];

__device__ float g_cos[TLEN * 64];
__device__ float g_sin[TLEN * 64];

// ---------------------------------------------------------------------------
__device__ __forceinline__ uint32_t s2u(const void* p) {
    return (uint32_t)__cvta_generic_to_shared(p);
}
#define SWZ(o) ((o) ^ (((o) >> 3) & 0x70))

__device__ __forceinline__ void cp_async16(uint32_t saddr, const void* gaddr) {
    asm volatile("cp.async.cg.shared.global [%0], [%1], 16;\n"
                 :: "r"(saddr), "l"(gaddr));
}
__device__ __forceinline__ void ldsm4(uint32_t* r, uint32_t addr) {
    asm volatile("ldmatrix.sync.aligned.m8n8.x4.shared.b16 {%0,%1,%2,%3}, [%4];"
                 : "=r"(r[0]), "=r"(r[1]), "=r"(r[2]), "=r"(r[3]) : "r"(addr));
}
__device__ __forceinline__ void ldsm4t(uint32_t* r, uint32_t addr) {
    asm volatile("ldmatrix.sync.aligned.m8n8.x4.trans.shared.b16 {%0,%1,%2,%3}, [%4];"
                 : "=r"(r[0]), "=r"(r[1]), "=r"(r[2]), "=r"(r[3]) : "r"(addr));
}
__device__ __forceinline__ void ldsm2(uint32_t* r, uint32_t addr) {
    asm volatile("ldmatrix.sync.aligned.m8n8.x2.shared.b16 {%0,%1}, [%2];"
                 : "=r"(r[0]), "=r"(r[1]) : "r"(addr));
}
__device__ __forceinline__ void mma16816(float* c, const uint32_t* a, const uint32_t* b) {
    asm volatile(
        "mma.sync.aligned.m16n8k16.row.col.f32.bf16.bf16.f32 "
        "{%0,%1,%2,%3}, {%4,%5,%6,%7}, {%8,%9}, {%0,%1,%2,%3};"
        : "+f"(c[0]), "+f"(c[1]), "+f"(c[2]), "+f"(c[3])
        : "r"(a[0]), "r"(a[1]), "r"(a[2]), "r"(a[3]), "r"(b[0]), "r"(b[1]));
}
__device__ __forceinline__ uint32_t packbf(float a, float b) {
    __nv_bfloat162 t(__float2bfloat16(a), __float2bfloat16(b));
    return *(uint32_t*)&t;
}

// ---------------------------------------------------------------------------
// split fp32 -> bf16 hi + bf16 lo
// ---------------------------------------------------------------------------
__global__ __launch_bounds__(256) void split_bf16(
    const float* __restrict__ src, __nv_bfloat16* __restrict__ hi,
    __nv_bfloat16* __restrict__ lo, int n4)
{
    int i = blockIdx.x * 256 + threadIdx.x;
    if (i >= n4) return;
    float4 v = ((const float4*)src)[i];
    __nv_bfloat16 h0 = __float2bfloat16(v.x);
    __nv_bfloat16 h1 = __float2bfloat16(v.y);
    __nv_bfloat16 h2 = __float2bfloat16(v.z);
    __nv_bfloat16 h3 = __float2bfloat16(v.w);
    ((__nv_bfloat162*)hi)[2*i]   = __nv_bfloat162(h0, h1);
    ((__nv_bfloat162*)hi)[2*i+1] = __nv_bfloat162(h2, h3);
    ((__nv_bfloat162*)lo)[2*i] = __nv_bfloat162(
        __float2bfloat16(v.x - __bfloat162float(h0)),
        __float2bfloat16(v.y - __bfloat162float(h1)));
    ((__nv_bfloat162*)lo)[2*i+1] = __nv_bfloat162(
        __float2bfloat16(v.z - __bfloat162float(h2)),
        __float2bfloat16(v.w - __bfloat162float(h3)));
}

// ---------------------------------------------------------------------------
// pack q_w|k_w|v_w (row-major [out,2048]) into one [3072,2048] hi/lo pair
// ---------------------------------------------------------------------------
__global__ __launch_bounds__(256) void prep_wqkv(
    const float* __restrict__ qw, const float* __restrict__ kw,
    const float* __restrict__ vw,
    __nv_bfloat16* __restrict__ hi, __nv_bfloat16* __restrict__ lo)
{
    int i = blockIdx.x * 256 + threadIdx.x;      // float4 index
    if (i >= NQKV * DIM / 4) return;
    int row = i >> 9;                            // 512 float4 per row
    int c4  = i & 511;
    const float* src;
    if (row < DIM)            src = qw + (size_t)row * DIM;
    else if (row < DIM + 512) src = kw + (size_t)(row - DIM) * DIM;
    else                      src = vw + (size_t)(row - DIM - 512) * DIM;
    float4 v = ((const float4*)src)[c4];
    __nv_bfloat16 h0 = __float2bfloat16(v.x);
    __nv_bfloat16 h1 = __float2bfloat16(v.y);
    __nv_bfloat16 h2 = __float2bfloat16(v.z);
    __nv_bfloat16 h3 = __float2bfloat16(v.w);
    ((__nv_bfloat162*)hi)[2*i]   = __nv_bfloat162(h0, h1);
    ((__nv_bfloat162*)hi)[2*i+1] = __nv_bfloat162(h2, h3);
    ((__nv_bfloat162*)lo)[2*i] = __nv_bfloat162(
        __float2bfloat16(v.x - __bfloat162float(h0)),
        __float2bfloat16(v.y - __bfloat162float(h1)));
    ((__nv_bfloat162*)lo)[2*i+1] = __nv_bfloat162(
        __float2bfloat16(v.z - __bfloat162float(h2)),
        __float2bfloat16(v.w - __bfloat162float(h3)));
}

// ---------------------------------------------------------------------------
// HMMA GEMM (NT), bf16 3-split. (validated R3/R5)
// ---------------------------------------------------------------------------
#define GEMM_SMEM (2 * 32768)

__global__ __launch_bounds__(256) void gemm_tc(
    const __nv_bfloat16* __restrict__ Ah, const __nv_bfloat16* __restrict__ Al,
    const __nv_bfloat16* __restrict__ Bh, const __nv_bfloat16* __restrict__ Bl,
    float* __restrict__ C, int M, int N, int K)
{
    extern __shared__ char sm[];
    const uint32_t smem_base = s2u(sm);
    const int tid = threadIdx.x;
    const int wid = tid >> 5, lane = tid & 31;
    const int wm = wid >> 2, wn = wid & 3;
    const int bm = blockIdx.y * 128, bn = blockIdx.x * 128;

    const int kstages = K >> 6;
    const int S = 3 * kstages;

    float acc[4][4][4];
#pragma unroll
    for (int i = 0; i < 4; ++i)
#pragma unroll
        for (int j = 0; j < 4; ++j)
#pragma unroll
            for (int t = 0; t < 4; ++t) acc[i][j][t] = 0.f;

    const int l16 = lane & 15;
    uint32_t aOff[4], aMsk[4], bOff[4], bMsk[4];
#pragma unroll
    for (int mt = 0; mt < 4; ++mt) {
        int row = wm * 64 + mt * 16 + l16;
        aOff[mt] = row * 128;
        aMsk[mt] = (row & 7) << 4;
    }
#pragma unroll
    for (int nt = 0; nt < 4; ++nt) {
        int row = wn * 32 + nt * 8 + (l16 & 7);
        bOff[nt] = row * 128;
        bMsk[nt] = (row & 7) << 4;
    }
    const uint32_t kbA = (lane >> 4) * 16;
    const uint32_t kbB = ((l16 >> 3) & 1) * 16;

    auto load_stage = [&](int s) {
        int p = s / kstages;
        int ks = (s - p * kstages) << 6;
        const __nv_bfloat16* Ap = (p == 1) ? Al : Ah;
        const __nv_bfloat16* Bp = (p == 2) ? Bl : Bh;
        uint32_t abuf = smem_base + (s & 1) * 32768;
        uint32_t bbuf = abuf + 16384;
#pragma unroll
        for (int i = 0; i < 4; ++i) {
            int c = tid + i * 256;
            int row = c >> 3, c16 = c & 7;
            cp_async16(abuf + SWZ(row * 128 + c16 * 16),
                       Ap + (size_t)(bm + row) * K + ks + c16 * 8);
        }
#pragma unroll
        for (int i = 0; i < 4; ++i) {
            int c = tid + i * 256;
            int row = c >> 3, c16 = c & 7;
            cp_async16(bbuf + SWZ(row * 128 + c16 * 16),
                       Bp + (size_t)(bn + row) * K + ks + c16 * 8);
        }
        asm volatile("cp.async.commit_group;");
    };

    load_stage(0);
    for (int s = 0; s < S; ++s) {
        if (s + 1 < S) {
            load_stage(s + 1);
            asm volatile("cp.async.wait_group 1;" ::: "memory");
        } else {
            asm volatile("cp.async.wait_group 0;" ::: "memory");
        }
        __syncthreads();

        uint32_t abuf = smem_base + (s & 1) * 32768;
        uint32_t bbuf = abuf + 16384;
#pragma unroll
        for (int kk = 0; kk < 4; ++kk) {
            uint32_t af[4][4], bfr[4][2];
            uint32_t ka = kk * 32 + kbA;
            uint32_t kb = kk * 32 + kbB;
#pragma unroll
            for (int mt = 0; mt < 4; ++mt)
                ldsm4(af[mt], abuf + aOff[mt] + (ka ^ aMsk[mt]));
#pragma unroll
            for (int nt = 0; nt < 4; ++nt)
                ldsm2(bfr[nt], bbuf + bOff[nt] + (kb ^ bMsk[nt]));
#pragma unroll
            for (int mt = 0; mt < 4; ++mt)
#pragma unroll
                for (int nt = 0; nt < 4; ++nt)
                    mma16816(acc[mt][nt], af[mt], bfr[nt]);
        }
        __syncthreads();
    }

    const int er = lane >> 2, ec = (lane & 3) * 2;
#pragma unroll
    for (int mt = 0; mt < 4; ++mt) {
#pragma unroll
        for (int nt = 0; nt < 4; ++nt) {
            int r0 = bm + wm * 64 + mt * 16 + er;
            int c0 = bn + wn * 32 + nt * 8 + ec;
            *(float2*)&C[(size_t)r0 * N + c0] =
                make_float2(acc[mt][nt][0], acc[mt][nt][1]);
            *(float2*)&C[(size_t)(r0 + 8) * N + c0] =
                make_float2(acc[mt][nt][2], acc[mt][nt][3]);
        }
    }
}

// ---------------------------------------------------------------------------
// RoPE tables (T x 64)
// ---------------------------------------------------------------------------
__global__ void rope_table_kernel(float* __restrict__ cs, float* __restrict__ sn)
{
    const int t = blockIdx.x, i = threadIdx.x;
    float base = 10000.f;
    if (TLEN > 1024) base = 10000.f * powf((float)TLEN / 1024.f, 128.f / 126.f);
    float l2b = log2f(base);
    float inv = exp2f(-(float)i * (l2b * (1.f / 64.f)));
    float ang = (float)t * inv;
    cs[t * 64 + i] = cosf(ang);
    sn[t * 64 + i] = sinf(ang);
}

// ---------------------------------------------------------------------------
// Fused RMSNorm + RoPE (+v split) from packed qkv, emitting bf16 hi/lo.
// 24 vectors per token: 16 q (norm+rope+gain), 4 k (norm+rope), 4 v (split).
// ---------------------------------------------------------------------------
__global__ __launch_bounds__(128) void norm_rope_kernel(
    const float* __restrict__ qkv, const float* __restrict__ q_gain,
    const float* __restrict__ cs, const float* __restrict__ sn,
    __nv_bfloat16* __restrict__ qh, __nv_bfloat16* __restrict__ ql,
    __nv_bfloat16* __restrict__ kh, __nv_bfloat16* __restrict__ kl,
    __nv_bfloat16* __restrict__ vh, __nv_bfloat16* __restrict__ vl)
{
    const int vec = blockIdx.x;
    const int hh = vec % 24;
    const int token = vec / 24;
    const int t = token % TLEN;
    const int tid = threadIdx.x;

    const float* src = qkv + (size_t)token * NQKV;
    __nv_bfloat16 *oh, *ol;
    size_t off;
    float gain;

    if (hh < NH) {
        src += hh * DH;
        off = ((size_t)token * NH + hh) * DH;
        oh = qh; ol = ql;
        gain = q_gain[hh] * (ATTN_SCALE * LOG2E);
    } else if (hh < NH + NKV) {
        src += DIM + (hh - NH) * DH;
        off = ((size_t)token * NKV + (hh - NH)) * DH;
        oh = kh; ol = kl;
        gain = 1.f;
    } else {
        src += DIM + NKV * DH + (hh - NH - NKV) * DH;
        off = ((size_t)token * NKV + (hh - NH - NKV)) * DH;
        float r = src[tid];
        __nv_bfloat16 hv = __float2bfloat16(r);
        vh[off + tid] = hv;
        vl[off + tid] = __float2bfloat16(r - __bfloat162float(hv));
        return;
    }

    float xv = src[tid];

    __shared__ float red[4];
    float s = xv * xv;
#pragma unroll
    for (int o = 16; o > 0; o >>= 1)
        s += __shfl_xor_sync(0xffffffffu, s, o);
    if ((tid & 31) == 0) red[tid >> 5] = s;
    __syncthreads();
    float tot = red[0] + red[1] + red[2] + red[3];
    float rn = rsqrtf(tot * (1.f / DH) + EPSF);
    float xn = xv * rn;

    __shared__ float buf[DH];
    buf[tid] = xn;
    __syncthreads();

    const int i = tid & 63;
    float c  = cs[t * 64 + i];
    float si = sn[t * 64 + i];
    float x1 = buf[i], x2 = buf[i + 64];
    float r = ((tid < 64) ? (x1 * c + x2 * si) : (-x1 * si + x2 * c)) * gain;

    __nv_bfloat16 hv = __float2bfloat16(r);
    oh[off + tid] = hv;
    ol[off + tid] = __float2bfloat16(r - __bfloat162float(hv));
}

// ---------------------------------------------------------------------------
// HMMA flash attention (causal, GQA), hi/lo split, optimized:
//  - Q fragments hoisted out of the kt loop (Q invariant per tile)
//  - KH/VH fragments shared across the two split passes that use them
//  - pair-fold load balance: CTA handles tiles (pr, 31-pr) -> 33 kt each
// ---------------------------------------------------------------------------
#define ATTN_SMEM (6 * 16384)

__global__ __launch_bounds__(128) void attn_mma(
    const __nv_bfloat16* __restrict__ qh, const __nv_bfloat16* __restrict__ ql,
    const __nv_bfloat16* __restrict__ kh, const __nv_bfloat16* __restrict__ kl,
    const __nv_bfloat16* __restrict__ vh, const __nv_bfloat16* __restrict__ vl,
    __nv_bfloat16* __restrict__ oh, __nv_bfloat16* __restrict__ ol)
{
    extern __shared__ char smc[];
    const uint32_t sQH = s2u(smc);
    const uint32_t sQL = sQH + 16384;
    const uint32_t sKH = sQL + 16384;
    const uint32_t sKL = sKH + 16384;
    const uint32_t sVH = sKL + 16384;
    const uint32_t sVL = sVH + 16384;

    const int pr = blockIdx.x;               // 0..15
    const int h = blockIdx.y, b = blockIdx.z;
    const int hkv = h >> 2;
    const int tid = threadIdx.x, wid = tid >> 5, lane = tid & 31;
    const int quad = lane >> 2, qx = lane & 3;

    const uint32_t aRow = wid * 16 + (lane & 15);
    const uint32_t aSwz = (aRow & 7) << 4;
    const uint32_t aKb  = (lane >> 4) * 16;
    const uint32_t kRowB = ((lane >> 4) & 1) * 8 + (lane & 7);
    const uint32_t kKb   = ((lane >> 3) & 1) * 16;
    const uint32_t vRowB = ((lane >> 3) & 1) * 8 + (lane & 7);
    const uint32_t vCb   = ((lane >> 4) & 1) * 16;

    for (int sel = 0; sel < 2; ++sel) {
        const int qb = sel ? (NQT - 1 - pr) : pr;
        const int q0 = qb * 64;

        __syncthreads();   // Q buffers free (prev tile compute done)
        for (int i = tid; i < 1024; i += 128) {
            int row = i >> 4, cb = (i & 15) * 16;
            uint32_t sw = row * 256 + (cb ^ ((row & 7) << 4));
            size_t g = ((size_t)(b * TLEN + q0 + row) * NH + h) * DH + (i & 15) * 8;
            cp_async16(sQH + sw, qh + g);
            cp_async16(sQL + sw, ql + g);
        }
        asm volatile("cp.async.commit_group;");
        asm volatile("cp.async.wait_group 0;" ::: "memory");
        __syncthreads();

        // hoist Q fragments
        uint32_t qfh[8][4], qfl[8][4];
#pragma unroll
        for (int kk = 0; kk < 8; ++kk) {
            ldsm4(qfh[kk], sQH + aRow * 256 + ((kk * 32 + aKb) ^ aSwz));
            ldsm4(qfl[kk], sQL + aRow * 256 + ((kk * 32 + aKb) ^ aSwz));
        }

        float acc[16][4];
#pragma unroll
        for (int j = 0; j < 16; ++j)
#pragma unroll
            for (int t = 0; t < 4; ++t) acc[j][t] = 0.f;
        float m0 = -1e30f, m1 = -1e30f, l0 = 0.f, l1 = 0.f;

        for (int kt = 0; kt <= qb; ++kt) {
            __syncthreads();
            for (int i = tid; i < 1024; i += 128) {
                int row = i >> 4, cb = (i & 15) * 16;
                uint32_t sw = row * 256 + (cb ^ ((row & 7) << 4));
                size_t g = ((size_t)(b * TLEN + kt * 64 + row) * NKV + hkv) * DH
                           + (i & 15) * 8;
                cp_async16(sKH + sw, kh + g);
                cp_async16(sKL + sw, kl + g);
                cp_async16(sVH + sw, vh + g);
                cp_async16(sVL + sw, vl + g);
            }
            asm volatile("cp.async.commit_group;");
            asm volatile("cp.async.wait_group 0;" ::: "memory");
            __syncthreads();

            // ---- S = QhKh + QlKh + QhKl (shared KH frags) ----
            float s[8][4];
#pragma unroll
            for (int j = 0; j < 8; ++j)
#pragma unroll
                for (int t = 0; t < 4; ++t) s[j][t] = 0.f;

#pragma unroll
            for (int kk = 0; kk < 8; ++kk) {
#pragma unroll
                for (int jj = 0; jj < 4; ++jj) {
                    uint32_t kr = jj * 16 + kRowB;
                    uint32_t off = kr * 256 + ((kk * 32 + kKb) ^ ((kr & 7) << 4));
                    uint32_t kf[4];
                    ldsm4(kf, sKH + off);
                    mma16816(s[2 * jj],     qfh[kk], kf);
                    mma16816(s[2 * jj + 1], qfh[kk], kf + 2);
                    mma16816(s[2 * jj],     qfl[kk], kf);
                    mma16816(s[2 * jj + 1], qfl[kk], kf + 2);
                    ldsm4(kf, sKL + off);
                    mma16816(s[2 * jj],     qfh[kk], kf);
                    mma16816(s[2 * jj + 1], qfh[kk], kf + 2);
                }
            }

            // ---- causal mask (diagonal tile) ----
            if (kt == qb) {
                int gr = wid * 16 + quad;
#pragma unroll
                for (int j = 0; j < 8; ++j) {
                    int gc = j * 8 + qx * 2;
                    if (gc     > gr)     s[j][0] = -1e30f;
                    if (gc + 1 > gr)     s[j][1] = -1e30f;
                    if (gc     > gr + 8) s[j][2] = -1e30f;
                    if (gc + 1 > gr + 8) s[j][3] = -1e30f;
                }
            }

            // ---- online softmax (base-2) ----
            float t0 = -1e30f, t1 = -1e30f;
#pragma unroll
            for (int j = 0; j < 8; ++j) {
                t0 = fmaxf(t0, fmaxf(s[j][0], s[j][1]));
                t1 = fmaxf(t1, fmaxf(s[j][2], s[j][3]));
            }
            t0 = fmaxf(t0, __shfl_xor_sync(0xffffffffu, t0, 1));
            t0 = fmaxf(t0, __shfl_xor_sync(0xffffffffu, t0, 2));
            t1 = fmaxf(t1, __shfl_xor_sync(0xffffffffu, t1, 1));
            t1 = fmaxf(t1, __shfl_xor_sync(0xffffffffu, t1, 2));
            float mn0 = fmaxf(m0, t0), mn1 = fmaxf(m1, t1);
            float sc0 = exp2f(m0 - mn0), sc1 = exp2f(m1 - mn1);
            m0 = mn0; m1 = mn1;

            uint32_t phA[8], phB[8], plA[8], plB[8];
            float ls0 = 0.f, ls1 = 0.f;
#pragma unroll
            for (int j = 0; j < 8; ++j) {
                float p0 = exp2f(s[j][0] - mn0);
                float p1 = exp2f(s[j][1] - mn0);
                float p2 = exp2f(s[j][2] - mn1);
                float p3 = exp2f(s[j][3] - mn1);
                ls0 += p0 + p1; ls1 += p2 + p3;
                __nv_bfloat16 h0 = __float2bfloat16(p0), h1 = __float2bfloat16(p1);
                __nv_bfloat16 h2 = __float2bfloat16(p2), h3 = __float2bfloat16(p3);
                __nv_bfloat162 a(h0, h1), bb(h2, h3);
                phA[j] = *(uint32_t*)&a; phB[j] = *(uint32_t*)&bb;
                plA[j] = packbf(p0 - __bfloat162float(h0), p1 - __bfloat162float(h1));
                plB[j] = packbf(p2 - __bfloat162float(h2), p3 - __bfloat162float(h3));
            }
            l0 = l0 * sc0 + ls0;
            l1 = l1 * sc1 + ls1;
#pragma unroll
            for (int j = 0; j < 16; ++j) {
                acc[j][0] *= sc0; acc[j][1] *= sc0;
                acc[j][2] *= sc1; acc[j][3] *= sc1;
            }

            // ---- O += PhVh + PlVh + PhVl (shared VH frags) ----
#pragma unroll
            for (int kk = 0; kk < 4; ++kk) {
                uint32_t aH[4] = {phA[2*kk], phB[2*kk], phA[2*kk+1], phB[2*kk+1]};
                uint32_t aL[4] = {plA[2*kk], plB[2*kk], plA[2*kk+1], plB[2*kk+1]};
                uint32_t vr = kk * 16 + vRowB;
                uint32_t vsw = (vr & 7) << 4;
#pragma unroll
                for (int jp = 0; jp < 8; ++jp) {
                    uint32_t off = vr * 256 + ((jp * 32 + vCb) ^ vsw);
                    uint32_t vf[4];
                    ldsm4t(vf, sVH + off);
                    mma16816(acc[2 * jp],     aH, vf);
                    mma16816(acc[2 * jp + 1], aH, vf + 2);
                    mma16816(acc[2 * jp],     aL, vf);
                    mma16816(acc[2 * jp + 1], aL, vf + 2);
                    ldsm4t(vf, sVL + off);
                    mma16816(acc[2 * jp],     aH, vf);
                    mma16816(acc[2 * jp + 1], aH, vf + 2);
                }
            }
        }

        // ---- epilogue ----
        l0 += __shfl_xor_sync(0xffffffffu, l0, 1);
        l0 += __shfl_xor_sync(0xffffffffu, l0, 2);
        l1 += __shfl_xor_sync(0xffffffffu, l1, 1);
        l1 += __shfl_xor_sync(0xffffffffu, l1, 2);
        float i0 = 1.f / l0, i1 = 1.f / l1;

        size_t tok0 = (size_t)(b * TLEN + q0 + wid * 16 + quad);
        size_t tok1 = tok0 + 8;
#pragma unroll
        for (int j = 0; j < 16; ++j) {
            int col = h * DH + j * 8 + qx * 2;
            float v0 = acc[j][0] * i0, v1 = acc[j][1] * i0;
            float v2 = acc[j][2] * i1, v3 = acc[j][3] * i1;
            __nv_bfloat16 h0 = __float2bfloat16(v0), h1 = __float2bfloat16(v1);
            __nv_bfloat16 h2 = __float2bfloat16(v2), h3 = __float2bfloat16(v3);
            *(__nv_bfloat162*)&oh[tok0 * DIM + col] = __nv_bfloat162(h0, h1);
            *(__nv_bfloat162*)&oh[tok1 * DIM + col] = __nv_bfloat162(h2, h3);
            *(__nv_bfloat162*)&ol[tok0 * DIM + col] =
                __nv_bfloat162(__float2bfloat16(v0 - __bfloat162float(h0)),
                               __float2bfloat16(v1 - __bfloat162float(h1)));
            *(__nv_bfloat162*)&ol[tok1 * DIM + col] =
                __nv_bfloat162(__float2bfloat16(v2 - __bfloat162float(h2)),
                               __float2bfloat16(v3 - __bfloat162float(h3)));
        }
    }
}

// ---------------------------------------------------------------------------
extern "C" void kernel_launch(void* const* d_in, const int* in_sizes, int n_in,
                              void* d_out, int out_size)
{
    const float* x  = (const float*)d_in[0];
    const float* qw = (const float*)d_in[1];
    const float* kw = (const float*)d_in[2];
    const float* vw = (const float*)d_in[3];
    const float* ow = (const float*)d_in[4];
    const float* qg = (const float*)d_in[5];
    float* out = (float*)d_out;

    float *gqkv, *gcos, *gsin;
    cudaGetSymbolAddress((void**)&gqkv, g_qkv);
    cudaGetSymbolAddress((void**)&gcos, g_cos);
    cudaGetSymbolAddress((void**)&gsin, g_sin);

    __nv_bfloat16 *xh, *xl, *wqh, *wql, *owh, *owl, *oh, *ol;
    __nv_bfloat16 *qbh, *qbl, *kbh, *kbl, *vbh, *vbl;
    cudaGetSymbolAddress((void**)&xh,  g_xh);    cudaGetSymbolAddress((void**)&xl,  g_xl);
    cudaGetSymbolAddress((void**)&wqh, g_wqkvh); cudaGetSymbolAddress((void**)&wql, g_wqkvl);
    cudaGetSymbolAddress((void**)&owh, g_owh);   cudaGetSymbolAddress((void**)&owl, g_owl);
    cudaGetSymbolAddress((void**)&oh,  g_oh);    cudaGetSymbolAddress((void**)&ol,  g_ol);
    cudaGetSymbolAddress((void**)&qbh, g_qbh);   cudaGetSymbolAddress((void**)&qbl, g_qbl);
    cudaGetSymbolAddress((void**)&kbh, g_kbh);   cudaGetSymbolAddress((void**)&kbl, g_kbl);
    cudaGetSymbolAddress((void**)&vbh, g_vbh);   cudaGetSymbolAddress((void**)&vbl, g_vbl);

    const int M = MTOT, K = DIM;

    cudaFuncSetAttribute(gemm_tc, cudaFuncAttributeMaxDynamicSharedMemorySize, GEMM_SMEM);
    cudaFuncSetAttribute(attn_mma, cudaFuncAttributeMaxDynamicSharedMemorySize, ATTN_SMEM);

    // launches ordered so ncu (-s 5) captures attn_mma
    rope_table_kernel<<<TLEN, 64>>>(gcos, gsin);                         // 0
    split_bf16<<<(M*K/4 + 255)/256, 256>>>(x, xh, xl, M*K/4);            // 1
    prep_wqkv<<<(NQKV*DIM/4 + 255)/256, 256>>>(qw, kw, vw, wqh, wql);    // 2
    gemm_tc<<<dim3(NQKV/128, M/128), 256, GEMM_SMEM>>>(                   // 3
        xh, xl, wqh, wql, gqkv, M, NQKV, K);
    norm_rope_kernel<<<M * 24, 128>>>(gqkv, qg, gcos, gsin,              // 4
                                      qbh, qbl, kbh, kbl, vbh, vbl);
    attn_mma<<<dim3(NQT/2, NH, BATCH), 128, ATTN_SMEM>>>(                 // 5 <- profiled
        qbh, qbl, kbh, kbl, vbh, vbl, oh, ol);
    split_bf16<<<(DIM*DIM/4 + 255)/256, 256>>>(ow, owh, owl, DIM*DIM/4); // 6
    gemm_tc<<<dim3(DIM/128, M/128), 256, GEMM_SMEM>>>(                    // 7
        oh, ol, owh, owl, out, M, DIM, K);
}